// round 10
// baseline (speedup 1.0000x reference)
#include <cuda_runtime.h>
#include <cstdint>

#define FULLMASK 0xffffffffu

// ----- scratch: __device__ globals (no runtime allocation) ------------------
__device__ float  g_sq[4*4096];
__device__ float4 g_hb4[4*4096*4];              // bottleneck feats [p][16f]
__device__ float  g_r[4*128*4096];              // residual branch
__device__ int    g_knn[4*4096*20];
__device__ float  g_allf[4*96*4096];

__device__ __forceinline__ void ffma2(unsigned long long &d, unsigned long long a, unsigned long long b) {
    asm("fma.rn.f32x2 %0, %1, %2, %0;" : "+l"(d) : "l"(a), "l"(b));
}
__device__ __forceinline__ unsigned long long pack2(float lo, float hi) {
    unsigned long long r; asm("mov.b64 %0, {%1, %2};" : "=l"(r) : "f"(lo), "f"(hi)); return r;
}
__device__ __forceinline__ float2 unpack2(unsigned long long v) {
    float2 f; asm("mov.b64 {%0, %1}, %2;" : "=f"(f.x), "=f"(f.y) : "l"(v)); return f;
}

// sorted top-20 insert, lanes 0..19 hold ascending (bd,bi); lax.top_k tie-break
__device__ __forceinline__ void topk_insert(float v, int id, float& bd, int& bi,
                                            float& thr, int& thri, int lane)
{
    unsigned m = __ballot_sync(FULLMASK, v < thr || (v == thr && id < thri));
    while (m) {
        int src = __ffs(m) - 1;
        float dn = __shfl_sync(FULLMASK, v, src);
        int  idn = __shfl_sync(FULLMASK, id, src);
        unsigned lt = __ballot_sync(FULLMASK, bd < dn || (bd == dn && bi < idn)) & 0xFFFFFu;
        int pos = __popc(lt);
        float pu = __shfl_up_sync(FULLMASK, bd, 1);
        int   iu = __shfl_up_sync(FULLMASK, bi, 1);
        if (lane < 20) {
            if (lane == pos)      { bd = dn; bi = idn; }
            else if (lane > pos)  { bd = pu; bi = iu; }
        }
        thr  = __shfl_sync(FULLMASK, bd, 19);
        thri = __shfl_sync(FULLMASK, bi, 19);
        m &= m - 1;
        m &= __ballot_sync(FULLMASK, v < thr || (v == thr && id < thri));
    }
}

// ============================================================================
// K1: sq, hb = relu(bn(Wbot@x)), r = relu(bn(Wres@x)). grid(64,2), 256 thr.
// ============================================================================
__global__ __launch_bounds__(256) void k_prep(
    const float* __restrict__ x,
    const float* __restrict__ Wres, const float* __restrict__ gres, const float* __restrict__ bres,
    const float* __restrict__ mres, const float* __restrict__ vres,
    const float* __restrict__ Wbot, const float* __restrict__ gbot, const float* __restrict__ bbot,
    const float* __restrict__ mbot, const float* __restrict__ vbot)
{
    __shared__ float4 sWr[64][16];
    __shared__ float4 sWb[16][16];
    __shared__ float sS[64], sT[64], sSb[16], sTb[16];
    const int tid = threadIdx.x;
    const int obase = blockIdx.y * 64;
    for (int i = tid; i < 1024; i += 256)
        sWr[i >> 4][i & 15] = ((const float4*)Wres)[(obase + (i >> 4)) * 16 + (i & 15)];
    sWb[tid >> 4][tid & 15] = ((const float4*)Wbot)[tid];
    if (tid < 64) {
        int o = obase + tid;
        float s = gres[o] * rsqrtf(vres[o] + 1e-5f);
        sS[tid] = s; sT[tid] = bres[o] - mres[o] * s;
    } else if (tid < 80) {
        int j = tid - 64;
        float s = gbot[j] * rsqrtf(vbot[j] + 1e-5f);
        sSb[j] = s; sTb[j] = bbot[j] - mbot[j] * s;
    }
    __syncthreads();

    const int p = blockIdx.x * 256 + tid;
    const int b = p >> 12, n = p & 4095;
    const float* xb = x + (size_t)b * 262144 + n;
    float xr[64]; float sqv = 0.f;
#pragma unroll
    for (int c = 0; c < 64; c++) { float v = xb[(size_t)c << 12]; xr[c] = v; sqv += v * v; }

    if (blockIdx.y == 0) {
        g_sq[p] = sqv;
        float h[16];
#pragma unroll
        for (int j = 0; j < 16; j++) {
            float acc = 0.f;
#pragma unroll
            for (int c4 = 0; c4 < 16; c4++) {
                float4 w = sWb[j][c4];
                acc += w.x * xr[4*c4] + w.y * xr[4*c4+1] + w.z * xr[4*c4+2] + w.w * xr[4*c4+3];
            }
            float y = sSb[j] * acc + sTb[j];
            h[j] = y > 0.f ? y : 0.f;
        }
        float4* hd = &g_hb4[(size_t)p * 4];
        hd[0] = make_float4(h[0], h[1], h[2], h[3]);
        hd[1] = make_float4(h[4], h[5], h[6], h[7]);
        hd[2] = make_float4(h[8], h[9], h[10], h[11]);
        hd[3] = make_float4(h[12], h[13], h[14], h[15]);
    }

    float* rp = g_r + (size_t)(b * 128 + obase) * 4096 + n;
    for (int o = 0; o < 64; o++) {
        float acc = 0.f;
#pragma unroll
        for (int c4 = 0; c4 < 16; c4++) {
            float4 w = sWr[o][c4];
            acc += w.x * xr[4*c4] + w.y * xr[4*c4+1] + w.z * xr[4*c4+2] + w.w * xr[4*c4+3];
        }
        float y = sS[o] * acc + sT[o];
        rp[(size_t)o << 12] = y > 0.f ? y : 0.f;
    }
}

// ============================================================================
// K2: FUSED distance GEMM + streaming top-20. Block = 64-row i-tile, loops
// all 64 j-tiles. Warp w's GEMM regs hold rows 8w..8w+7 → merge from regs.
// No 256MB d2 scratch, no separate topk kernel.
// ============================================================================
__global__ __launch_bounds__(256, 2) void k_d2topk(const float* __restrict__ x)
{
    __shared__ __align__(16) float As[4096];   // [c][i] 64x64, resident
    __shared__ __align__(16) float Bs[4096];   // [c][j] 64x64, single buffer
    const int b = blockIdx.y, i0 = blockIdx.x * 64;
    const int tid = threadIdx.x;
    const int tx = tid & 15, ty = tid >> 4;
    const int lane = tid & 31, w = tid >> 5;
    const float4* xb = (const float4*)(x + (size_t)b * 262144);

    // preload As (i-tile) and Bs (j-tile 0)
#pragma unroll
    for (int t = 0; t < 4; t++) {
        int s = tid + t * 256;
        int c = s >> 4, r4 = s & 15;
        ((float4*)As)[c * 16 + r4] = xb[c * 1024 + (i0 >> 2) + r4];
        ((float4*)Bs)[c * 16 + r4] = xb[c * 1024 + r4];
    }

    // per-thread row norms (rows ty*4+mm), loop-invariant
    float sqi_r[4];
#pragma unroll
    for (int mm = 0; mm < 4; mm++) sqi_r[mm] = g_sq[b * 4096 + i0 + ty * 4 + mm];

    const float INF = __int_as_float(0x7f800000);
    // top-20 state: 8 rows per warp (mm 0..3 = lanes<16 rows, 4+mm = lanes>=16)
    float bd[8]; int bi[8]; float thr[8]; int thri[8];
#pragma unroll
    for (int q = 0; q < 8; q++) { bd[q] = INF; bi[q] = 0x7fffffff; thr[q] = INF; thri[q] = 0x7fffffff; }

    for (int t = 0; t < 64; t++) {
        __syncthreads();   // Bs for tile t visible

        // prefetch next j-tile into registers (hidden under GEMM)
        float4 pf[4];
        if (t < 63) {
            int j4 = (t + 1) * 16;
#pragma unroll
            for (int u = 0; u < 4; u++) {
                int s = tid + u * 256;
                pf[u] = xb[(s >> 4) * 1024 + j4 + (s & 15)];
            }
        }

        unsigned long long acc[4][2] = {{0ull,0ull},{0ull,0ull},{0ull,0ull},{0ull,0ull}};
#pragma unroll 8
        for (int k = 0; k < 64; k++) {
            float4 av = *(const float4*)(As + k * 64 + ty * 4);
            float4 bv = *(const float4*)(Bs + k * 64 + tx * 4);
            unsigned long long b01 = pack2(bv.x, bv.y), b23 = pack2(bv.z, bv.w);
            unsigned long long aa;
            aa = pack2(av.x, av.x); ffma2(acc[0][0], aa, b01); ffma2(acc[0][1], aa, b23);
            aa = pack2(av.y, av.y); ffma2(acc[1][0], aa, b01); ffma2(acc[1][1], aa, b23);
            aa = pack2(av.z, av.z); ffma2(acc[2][0], aa, b01); ffma2(acc[2][1], aa, b23);
            aa = pack2(av.w, av.w); ffma2(acc[3][0], aa, b01); ffma2(acc[3][1], aa, b23);
        }

        __syncthreads();   // all warps done reading Bs
        if (t < 63) {
#pragma unroll
            for (int u = 0; u < 4; u++) {
                int s = tid + u * 256;
                ((float4*)Bs)[(s >> 4) * 16 + (s & 15)] = pf[u];
            }
        }

        // finalize d2 values (identical expression/order as unfused version)
        const int j0 = t * 64;
        float4 sqj = ((const float4*)(g_sq + b * 4096 + j0))[tx];
        float val[4][4];
#pragma unroll
        for (int mm = 0; mm < 4; mm++) {
            float2 p0 = unpack2(acc[mm][0]), p1 = unpack2(acc[mm][1]);
            float sqi = sqi_r[mm];
            val[mm][0] = sqi + sqj.x - 2.f * p0.x;
            val[mm][1] = sqi + sqj.y - 2.f * p0.y;
            val[mm][2] = sqi + sqj.z - 2.f * p1.x;
            val[mm][3] = sqi + sqj.w - 2.f * p1.y;
        }

        // merge into per-warp top-20 (half-warp masked with INF/INT_MAX)
#pragma unroll
        for (int mm = 0; mm < 4; mm++) {
#pragma unroll
            for (int u = 0; u < 4; u++) {
                bool act = (lane < 16);
                float v = act ? val[mm][u] : INF;
                int  id = act ? (j0 + lane * 4 + u) : 0x7fffffff;
                topk_insert(v, id, bd[mm], bi[mm], thr[mm], thri[mm], lane);
            }
#pragma unroll
            for (int u = 0; u < 4; u++) {
                bool act = (lane >= 16);
                float v = act ? val[mm][u] : INF;
                int  id = act ? (j0 + (lane - 16) * 4 + u) : 0x7fffffff;
                topk_insert(v, id, bd[4 + mm], bi[4 + mm], thr[4 + mm], thri[4 + mm], lane);
            }
        }
    }

    if (lane < 20) {
#pragma unroll
        for (int q = 0; q < 8; q++) {
            int row = i0 + w * 8 + q;
            g_knn[(size_t)(b * 4096 + row) * 20 + lane] = bi[q];
        }
    }
}

// ============================================================================
// K3: warp/point edge convs; weights staged in padded smem.
// allf channels: [0..31]=o1, [32..63]=o2, [64..79]=max_k nb, [80..95]=ctr.
// ============================================================================
__global__ __launch_bounds__(256, 4) void k_gcn(
    const float* __restrict__ Wg1, const float* __restrict__ g1c, const float* __restrict__ b1c,
    const float* __restrict__ m1c, const float* __restrict__ v1c,
    const float* __restrict__ Wg2, const float* __restrict__ g2c, const float* __restrict__ b2c,
    const float* __restrict__ m2c, const float* __restrict__ v2c)
{
    __shared__ float sW1[32][33], sW2[32][33];
    __shared__ float sBN[4][32];
    __shared__ float4 Fb[8][21][4];
    const int tid = threadIdx.x, w = tid >> 5, lane = tid & 31;
    const int p = blockIdx.x * 8 + w, b = p >> 12, n = p & 4095;

    for (int i = tid; i < 1024; i += 256) {
        sW1[i >> 5][i & 31] = Wg1[i];
        sW2[i >> 5][i & 31] = Wg2[i];
    }
    if (tid < 32) {
        float s1v = g1c[tid] * rsqrtf(v1c[tid] + 1e-5f);
        float s2v = g2c[tid] * rsqrtf(v2c[tid] + 1e-5f);
        sBN[0][tid] = s1v; sBN[1][tid] = b1c[tid] - m1c[tid] * s1v;
        sBN[2][tid] = s2v; sBN[3][tid] = b2c[tid] - m2c[tid] * s2v;
    }
    __syncthreads();

    unsigned long long w1p[8], w2p[8];
#pragma unroll
    for (int c = 0; c < 8; c++) {
        w1p[c] = pack2(sW1[lane][2*c], sW1[lane][2*c + 1]);
        w2p[c] = pack2(sW2[lane][2*c], sW2[lane][2*c + 1]);
    }
    const float s1 = sBN[0][lane], t1 = sBN[1][lane];
    const float s2 = sBN[2][lane], t2 = sBN[3][lane];

    int id = (lane < 20) ? g_knn[(size_t)p * 20 + lane] : n;
#pragma unroll
    for (int it = 0; it < 3; it++) {
        int pc = it * 32 + lane;
        int k = pc >> 2;
        int srcn = __shfl_sync(FULLMASK, id, (k < 24) ? k : 0);
        if (pc < 84) Fb[w][k][pc & 3] = g_hb4[(size_t)(b * 4096 + srcn) * 4 + (pc & 3)];
    }
    __syncwarp();

    float cd1 = 0.f, cd2 = 0.f;
    {
        const float* cp = (const float*)Fb[w][20];
#pragma unroll
        for (int c = 0; c < 16; c++) {
            float cv = cp[c];
            cd1 += sW1[lane][16 + c] * cv;
            cd2 += sW2[lane][16 + c] * cv;
        }
    }

    const float NINF = __int_as_float(0xff800000);
    float o1 = NINF, o2 = NINF;
#pragma unroll
    for (int k = 0; k < 20; k++) {
        const float4* fq = Fb[w][k];
        float4 f0 = fq[0], f1 = fq[1], f2 = fq[2], f3 = fq[3];
        unsigned long long fp[8];
        fp[0] = pack2(f0.x, f0.y); fp[1] = pack2(f0.z, f0.w);
        fp[2] = pack2(f1.x, f1.y); fp[3] = pack2(f1.z, f1.w);
        fp[4] = pack2(f2.x, f2.y); fp[5] = pack2(f2.z, f2.w);
        fp[6] = pack2(f3.x, f3.y); fp[7] = pack2(f3.z, f3.w);

        unsigned long long a0 = 0ull, a1 = 0ull;
#pragma unroll
        for (int c = 0; c < 8; c += 2) { ffma2(a0, w1p[c], fp[c]); ffma2(a1, w1p[c+1], fp[c+1]); }
        float2 r0 = unpack2(a0), r1 = unpack2(a1);
        float y1 = s1 * (cd1 + (r0.x + r0.y) + (r1.x + r1.y)) + t1;
        y1 = (y1 > 0.f) ? y1 : 0.2f * y1;
        o1 = fmaxf(o1, y1);

        if ((k & 1) == 0) {
            unsigned long long c0 = 0ull, c1 = 0ull;
#pragma unroll
            for (int c = 0; c < 8; c += 2) { ffma2(c0, w2p[c], fp[c]); ffma2(c1, w2p[c+1], fp[c+1]); }
            float2 q0 = unpack2(c0), q1 = unpack2(c1);
            float y2 = s2 * (cd2 + (q0.x + q0.y) + (q1.x + q1.y)) + t2;
            y2 = (y2 > 0.f) ? y2 : 0.2f * y2;
            o2 = fmaxf(o2, y2);
        }
    }

    float gm;
    if (lane < 16) {
        gm = NINF;
#pragma unroll
        for (int k = 0; k < 20; k++) gm = fmaxf(gm, ((const float*)Fb[w][k])[lane]);
    } else {
        gm = ((const float*)Fb[w][20])[lane - 16];
    }

    float* ap = g_allf + (size_t)b * 96 * 4096 + n;
    ap[(size_t)lane * 4096]        = o1;
    ap[(size_t)(32 + lane) * 4096] = o2;
    ap[(size_t)(64 + lane) * 4096] = gm;
}

// ============================================================================
// K4: out = relu(bn(Wdec@allf)) + r. grid(64,2), 256 thr.
// ============================================================================
__global__ __launch_bounds__(256) void k_dec(
    const float* __restrict__ Wdec, const float* __restrict__ gd, const float* __restrict__ bdc,
    const float* __restrict__ md, const float* __restrict__ vd, float* __restrict__ out)
{
    __shared__ float sW[64][96];
    __shared__ float sS[64], sT[64];
    const int tid = threadIdx.x;
    const int obase = blockIdx.y * 64;
    for (int i = tid; i < 6144; i += 256)
        sW[i / 96][i % 96] = Wdec[(obase + i / 96) * 96 + (i % 96)];
    if (tid < 64) {
        int o = obase + tid;
        float s = gd[o] * rsqrtf(vd[o] + 1e-5f);
        sS[tid] = s; sT[tid] = bdc[o] - md[o] * s;
    }
    __syncthreads();

    const int p = blockIdx.x * 256 + tid;
    const int b = p >> 12, n = p & 4095;
    float a[96];
    const float* ac = g_allf + (size_t)b * 96 * 4096 + n;
#pragma unroll
    for (int c = 0; c < 96; c++) a[c] = ac[(size_t)c * 4096];

    for (int o = 0; o < 64; o++) {
        float acc = 0.f;
#pragma unroll
        for (int c = 0; c < 96; c++) acc += sW[o][c] * a[c];
        float y = sS[o] * acc + sT[o];
        y = (y > 0.f) ? y : 0.f;
        size_t oi = (size_t)(b * 128 + obase + o) * 4096 + n;
        out[oi] = y + g_r[oi];
    }
}

// ============================================================================
extern "C" void kernel_launch(void* const* d_in, const int* in_sizes, int n_in,
                              void* d_out, int out_size)
{
    const float* x = (const float*)d_in[0];
    k_prep<<<dim3(64, 2), 256>>>(x,
        (const float*)d_in[1], (const float*)d_in[2], (const float*)d_in[3],
        (const float*)d_in[4], (const float*)d_in[5],
        (const float*)d_in[6], (const float*)d_in[7], (const float*)d_in[8],
        (const float*)d_in[9], (const float*)d_in[10]);
    k_d2topk<<<dim3(64, 4), 256>>>(x);
    k_gcn<<<2048, 256>>>(
        (const float*)d_in[11], (const float*)d_in[12], (const float*)d_in[13],
        (const float*)d_in[14], (const float*)d_in[15],
        (const float*)d_in[16], (const float*)d_in[17], (const float*)d_in[18],
        (const float*)d_in[19], (const float*)d_in[20]);
    k_dec<<<dim3(64, 2), 256>>>(
        (const float*)d_in[21], (const float*)d_in[22], (const float*)d_in[23],
        (const float*)d_in[24], (const float*)d_in[25], (float*)d_out);
}

// round 12
// speedup vs baseline: 1.4606x; 1.4606x over previous
#include <cuda_runtime.h>
#include <cstdint>

#define FULLMASK 0xffffffffu

// ----- scratch: __device__ globals (no runtime allocation) ------------------
__device__ float  g_sq[4*4096];
__device__ float4 g_hb4[4*4096*4];              // bottleneck feats [p][16f]
__device__ float  g_r[4*128*4096];              // residual branch
__device__ float4 g_d2[(size_t)4*4096*1024];    // 256MB distance matrix
__device__ int    g_knn[4*4096*20];
__device__ float  g_allf[4*96*4096];

__device__ __forceinline__ void ffma2(unsigned long long &d, unsigned long long a, unsigned long long b) {
    asm("fma.rn.f32x2 %0, %1, %2, %0;" : "+l"(d) : "l"(a), "l"(b));
}
__device__ __forceinline__ unsigned long long pack2(float lo, float hi) {
    unsigned long long r; asm("mov.b64 %0, {%1, %2};" : "=l"(r) : "f"(lo), "f"(hi)); return r;
}
__device__ __forceinline__ float2 unpack2(unsigned long long v) {
    float2 f; asm("mov.b64 {%0, %1}, %2;" : "=f"(f.x), "=f"(f.y) : "l"(v)); return f;
}

// ============================================================================
// K1: sq, hb = relu(bn(Wbot@x)), r = relu(bn(Wres@x)). grid(64,2), 256 thr.
// ============================================================================
__global__ __launch_bounds__(256) void k_prep(
    const float* __restrict__ x,
    const float* __restrict__ Wres, const float* __restrict__ gres, const float* __restrict__ bres,
    const float* __restrict__ mres, const float* __restrict__ vres,
    const float* __restrict__ Wbot, const float* __restrict__ gbot, const float* __restrict__ bbot,
    const float* __restrict__ mbot, const float* __restrict__ vbot)
{
    __shared__ float4 sWr[64][16];
    __shared__ float4 sWb[16][16];
    __shared__ float sS[64], sT[64], sSb[16], sTb[16];
    const int tid = threadIdx.x;
    const int obase = blockIdx.y * 64;
    for (int i = tid; i < 1024; i += 256)
        sWr[i >> 4][i & 15] = ((const float4*)Wres)[(obase + (i >> 4)) * 16 + (i & 15)];
    sWb[tid >> 4][tid & 15] = ((const float4*)Wbot)[tid];
    if (tid < 64) {
        int o = obase + tid;
        float s = gres[o] * rsqrtf(vres[o] + 1e-5f);
        sS[tid] = s; sT[tid] = bres[o] - mres[o] * s;
    } else if (tid < 80) {
        int j = tid - 64;
        float s = gbot[j] * rsqrtf(vbot[j] + 1e-5f);
        sSb[j] = s; sTb[j] = bbot[j] - mbot[j] * s;
    }
    __syncthreads();

    const int p = blockIdx.x * 256 + tid;
    const int b = p >> 12, n = p & 4095;
    const float* xb = x + (size_t)b * 262144 + n;
    float xr[64]; float sqv = 0.f;
#pragma unroll
    for (int c = 0; c < 64; c++) { float v = xb[(size_t)c << 12]; xr[c] = v; sqv += v * v; }

    if (blockIdx.y == 0) {
        g_sq[p] = sqv;
        float h[16];
#pragma unroll
        for (int j = 0; j < 16; j++) {
            float acc = 0.f;
#pragma unroll
            for (int c4 = 0; c4 < 16; c4++) {
                float4 w = sWb[j][c4];
                acc += w.x * xr[4*c4] + w.y * xr[4*c4+1] + w.z * xr[4*c4+2] + w.w * xr[4*c4+3];
            }
            float y = sSb[j] * acc + sTb[j];
            h[j] = y > 0.f ? y : 0.f;
        }
        float4* hd = &g_hb4[(size_t)p * 4];
        hd[0] = make_float4(h[0], h[1], h[2], h[3]);
        hd[1] = make_float4(h[4], h[5], h[6], h[7]);
        hd[2] = make_float4(h[8], h[9], h[10], h[11]);
        hd[3] = make_float4(h[12], h[13], h[14], h[15]);
    }

    float* rp = g_r + (size_t)(b * 128 + obase) * 4096 + n;
    for (int o = 0; o < 64; o++) {
        float acc = 0.f;
#pragma unroll
        for (int c4 = 0; c4 < 16; c4++) {
            float4 w = sWr[o][c4];
            acc += w.x * xr[4*c4] + w.y * xr[4*c4+1] + w.z * xr[4*c4+2] + w.w * xr[4*c4+3];
        }
        float y = sS[o] * acc + sT[o];
        rp[(size_t)o << 12] = y > 0.f ? y : 0.f;
    }
}

// ============================================================================
// K2: d2 = sq_i + sq_j - 2<x_i,x_j>. 64x64x64 tile, 256 thr, 4x4/thr, f32x2.
// ============================================================================
__global__ __launch_bounds__(256) void k_d2(const float* __restrict__ x)
{
    __shared__ __align__(16) float As[4096];   // [c][i]
    __shared__ __align__(16) float Bs[4096];   // [c][j]
    const int b = blockIdx.z, i0 = blockIdx.y * 64, j0 = blockIdx.x * 64;
    const int tid = threadIdx.x;
    const float4* xb = (const float4*)(x + (size_t)b * 262144);
#pragma unroll
    for (int t = 0; t < 4; t++) {
        int s = tid + t * 256;
        int c = s >> 4, r4 = s & 15;
        ((float4*)As)[c * 16 + r4] = xb[c * 1024 + (i0 >> 2) + r4];
        ((float4*)Bs)[c * 16 + r4] = xb[c * 1024 + (j0 >> 2) + r4];
    }
    __syncthreads();

    const int tx = tid & 15, ty = tid >> 4;
    unsigned long long acc[4][2] = {{0ull,0ull},{0ull,0ull},{0ull,0ull},{0ull,0ull}};
#pragma unroll 16
    for (int k = 0; k < 64; k++) {
        float4 av = *(const float4*)(As + k * 64 + ty * 4);
        float4 bv = *(const float4*)(Bs + k * 64 + tx * 4);
        unsigned long long b01 = pack2(bv.x, bv.y), b23 = pack2(bv.z, bv.w);
        unsigned long long aa;
        aa = pack2(av.x, av.x); ffma2(acc[0][0], aa, b01); ffma2(acc[0][1], aa, b23);
        aa = pack2(av.y, av.y); ffma2(acc[1][0], aa, b01); ffma2(acc[1][1], aa, b23);
        aa = pack2(av.z, av.z); ffma2(acc[2][0], aa, b01); ffma2(acc[2][1], aa, b23);
        aa = pack2(av.w, av.w); ffma2(acc[3][0], aa, b01); ffma2(acc[3][1], aa, b23);
    }

    float4 sqj = ((const float4*)(g_sq + b * 4096 + j0))[tx];
    const int rbase = b * 4096 + i0 + ty * 4;
#pragma unroll
    for (int mm = 0; mm < 4; mm++) {
        float2 p0 = unpack2(acc[mm][0]), p1 = unpack2(acc[mm][1]);
        float sqi = g_sq[rbase + mm];
        float4 o;
        o.x = sqi + sqj.x - 2.f * p0.x;
        o.y = sqi + sqj.y - 2.f * p0.y;
        o.z = sqi + sqj.z - 2.f * p1.x;
        o.w = sqi + sqj.w - 2.f * p1.y;
        g_d2[(size_t)(rbase + mm) * 1024 + (j0 >> 2) + tx] = o;
    }
}

// ============================================================================
// K3: top-20 ascending (d2, idx) per row — lax.top_k semantics.
// Gate: one conservative ballot per float4 (min4 <= thr); exact per-value
// path only when the gate fires.
// ============================================================================
__global__ __launch_bounds__(256) void k_topk()
{
    const int gw = (blockIdx.x * 256 + threadIdx.x) >> 5;
    const int lane = threadIdx.x & 31;
    const float4* row = g_d2 + (size_t)gw * 1024;
    const float INF = __int_as_float(0x7f800000);
    float bd = INF; int bi = 0x7fffffff;
    float thr = INF; int thri = 0x7fffffff;
    for (int base = 0; base < 1024; base += 32) {
        float4 v4 = row[base + lane];
        int id0 = (base + lane) << 2;
        float mn = fminf(fminf(v4.x, v4.y), fminf(v4.z, v4.w));
        if (__ballot_sync(FULLMASK, mn <= thr)) {
            float vv[4] = {v4.x, v4.y, v4.z, v4.w};
#pragma unroll
            for (int j = 0; j < 4; j++) {
                float v = vv[j]; int id = id0 + j;
                unsigned m = __ballot_sync(FULLMASK, v < thr || (v == thr && id < thri));
                while (m) {
                    int src = __ffs(m) - 1;
                    float dn = __shfl_sync(FULLMASK, v, src);
                    int  idn = __shfl_sync(FULLMASK, id, src);
                    unsigned lt = __ballot_sync(FULLMASK, bd < dn || (bd == dn && bi < idn)) & 0xFFFFFu;
                    int pos = __popc(lt);
                    float pu = __shfl_up_sync(FULLMASK, bd, 1);
                    int   iu = __shfl_up_sync(FULLMASK, bi, 1);
                    if (lane < 20) {
                        if (lane == pos)      { bd = dn; bi = idn; }
                        else if (lane > pos)  { bd = pu; bi = iu; }
                    }
                    thr  = __shfl_sync(FULLMASK, bd, 19);
                    thri = __shfl_sync(FULLMASK, bi, 19);
                    m &= m - 1;
                    m &= __ballot_sync(FULLMASK, v < thr || (v == thr && id < thri));
                }
            }
        }
    }
    if (lane < 20) g_knn[(size_t)gw * 20 + lane] = bi;
}

// ============================================================================
// K4: warp/point edge convs; weights staged in padded smem.
// allf channels: [0..31]=o1, [32..63]=o2, [64..79]=max_k nb, [80..95]=ctr.
// ============================================================================
__global__ __launch_bounds__(256, 4) void k_gcn(
    const float* __restrict__ Wg1, const float* __restrict__ g1c, const float* __restrict__ b1c,
    const float* __restrict__ m1c, const float* __restrict__ v1c,
    const float* __restrict__ Wg2, const float* __restrict__ g2c, const float* __restrict__ b2c,
    const float* __restrict__ m2c, const float* __restrict__ v2c)
{
    __shared__ float sW1[32][33], sW2[32][33];
    __shared__ float sBN[4][32];
    __shared__ float4 Fb[8][21][4];
    const int tid = threadIdx.x, w = tid >> 5, lane = tid & 31;
    const int p = blockIdx.x * 8 + w, b = p >> 12, n = p & 4095;

    for (int i = tid; i < 1024; i += 256) {
        sW1[i >> 5][i & 31] = Wg1[i];
        sW2[i >> 5][i & 31] = Wg2[i];
    }
    if (tid < 32) {
        float s1v = g1c[tid] * rsqrtf(v1c[tid] + 1e-5f);
        float s2v = g2c[tid] * rsqrtf(v2c[tid] + 1e-5f);
        sBN[0][tid] = s1v; sBN[1][tid] = b1c[tid] - m1c[tid] * s1v;
        sBN[2][tid] = s2v; sBN[3][tid] = b2c[tid] - m2c[tid] * s2v;
    }
    __syncthreads();

    unsigned long long w1p[8], w2p[8];
#pragma unroll
    for (int c = 0; c < 8; c++) {
        w1p[c] = pack2(sW1[lane][2*c], sW1[lane][2*c + 1]);
        w2p[c] = pack2(sW2[lane][2*c], sW2[lane][2*c + 1]);
    }
    const float s1 = sBN[0][lane], t1 = sBN[1][lane];
    const float s2 = sBN[2][lane], t2 = sBN[3][lane];

    int id = (lane < 20) ? g_knn[(size_t)p * 20 + lane] : n;
#pragma unroll
    for (int it = 0; it < 3; it++) {
        int pc = it * 32 + lane;
        int k = pc >> 2;
        int srcn = __shfl_sync(FULLMASK, id, (k < 24) ? k : 0);
        if (pc < 84) Fb[w][k][pc & 3] = g_hb4[(size_t)(b * 4096 + srcn) * 4 + (pc & 3)];
    }
    __syncwarp();

    float cd1 = 0.f, cd2 = 0.f;
    {
        const float* cp = (const float*)Fb[w][20];
#pragma unroll
        for (int c = 0; c < 16; c++) {
            float cv = cp[c];
            cd1 += sW1[lane][16 + c] * cv;
            cd2 += sW2[lane][16 + c] * cv;
        }
    }

    const float NINF = __int_as_float(0xff800000);
    float o1 = NINF, o2 = NINF;
#pragma unroll
    for (int k = 0; k < 20; k++) {
        const float4* fq = Fb[w][k];
        float4 f0 = fq[0], f1 = fq[1], f2 = fq[2], f3 = fq[3];
        unsigned long long fp[8];
        fp[0] = pack2(f0.x, f0.y); fp[1] = pack2(f0.z, f0.w);
        fp[2] = pack2(f1.x, f1.y); fp[3] = pack2(f1.z, f1.w);
        fp[4] = pack2(f2.x, f2.y); fp[5] = pack2(f2.z, f2.w);
        fp[6] = pack2(f3.x, f3.y); fp[7] = pack2(f3.z, f3.w);

        unsigned long long a0 = 0ull, a1 = 0ull;
#pragma unroll
        for (int c = 0; c < 8; c += 2) { ffma2(a0, w1p[c], fp[c]); ffma2(a1, w1p[c+1], fp[c+1]); }
        float2 r0 = unpack2(a0), r1 = unpack2(a1);
        float y1 = s1 * (cd1 + (r0.x + r0.y) + (r1.x + r1.y)) + t1;
        y1 = (y1 > 0.f) ? y1 : 0.2f * y1;
        o1 = fmaxf(o1, y1);

        if ((k & 1) == 0) {
            unsigned long long c0 = 0ull, c1 = 0ull;
#pragma unroll
            for (int c = 0; c < 8; c += 2) { ffma2(c0, w2p[c], fp[c]); ffma2(c1, w2p[c+1], fp[c+1]); }
            float2 q0 = unpack2(c0), q1 = unpack2(c1);
            float y2 = s2 * (cd2 + (q0.x + q0.y) + (q1.x + q1.y)) + t2;
            y2 = (y2 > 0.f) ? y2 : 0.2f * y2;
            o2 = fmaxf(o2, y2);
        }
    }

    float gm;
    if (lane < 16) {
        gm = NINF;
#pragma unroll
        for (int k = 0; k < 20; k++) gm = fmaxf(gm, ((const float*)Fb[w][k])[lane]);
    } else {
        gm = ((const float*)Fb[w][20])[lane - 16];
    }

    float* ap = g_allf + (size_t)b * 96 * 4096 + n;
    ap[(size_t)lane * 4096]        = o1;
    ap[(size_t)(32 + lane) * 4096] = o2;
    ap[(size_t)(64 + lane) * 4096] = gm;
}

// ============================================================================
// K5: out = relu(bn(Wdec@allf)) + r — tiled GEMM 64x64x96, 4x4/thr, f32x2.
// grid(64 n-tiles, 2 o-tiles, 4 b).
// ============================================================================
__global__ __launch_bounds__(256) void k_dec(
    const float* __restrict__ Wdec, const float* __restrict__ gd, const float* __restrict__ bdc,
    const float* __restrict__ md, const float* __restrict__ vd, float* __restrict__ out)
{
    __shared__ __align__(16) float sA[96 * 64];   // [c][o]
    __shared__ __align__(16) float sB[96 * 64];   // [c][n]
    __shared__ float sS[64], sT[64];
    const int b = blockIdx.z, o0 = blockIdx.y * 64, n0 = blockIdx.x * 64;
    const int tid = threadIdx.x;

    // W transposed into smem: conflict-free stores (consecutive tid -> consecutive o)
    for (int i = tid; i < 6144; i += 256) {
        int c = i >> 6, o = i & 63;
        sA[c * 64 + o] = Wdec[(o0 + o) * 96 + c];
    }
    const float4* ab = (const float4*)(g_allf + (size_t)b * 96 * 4096);
    for (int i = tid; i < 1536; i += 256) {        // 96 rows x 16 float4
        int c = i >> 4, r4 = i & 15;
        ((float4*)sB)[c * 16 + r4] = ab[c * 1024 + (n0 >> 2) + r4];
    }
    if (tid < 64) {
        int o = o0 + tid;
        float s = gd[o] * rsqrtf(vd[o] + 1e-5f);
        sS[tid] = s; sT[tid] = bdc[o] - md[o] * s;
    }
    __syncthreads();

    const int tx = tid & 15, ty = tid >> 4;
    unsigned long long acc[4][2] = {{0ull,0ull},{0ull,0ull},{0ull,0ull},{0ull,0ull}};
#pragma unroll 8
    for (int k = 0; k < 96; k++) {
        float4 av = *(const float4*)(sA + k * 64 + ty * 4);
        float4 bv = *(const float4*)(sB + k * 64 + tx * 4);
        unsigned long long b01 = pack2(bv.x, bv.y), b23 = pack2(bv.z, bv.w);
        unsigned long long aa;
        aa = pack2(av.x, av.x); ffma2(acc[0][0], aa, b01); ffma2(acc[0][1], aa, b23);
        aa = pack2(av.y, av.y); ffma2(acc[1][0], aa, b01); ffma2(acc[1][1], aa, b23);
        aa = pack2(av.z, av.z); ffma2(acc[2][0], aa, b01); ffma2(acc[2][1], aa, b23);
        aa = pack2(av.w, av.w); ffma2(acc[3][0], aa, b01); ffma2(acc[3][1], aa, b23);
    }

#pragma unroll
    for (int mm = 0; mm < 4; mm++) {
        int o = ty * 4 + mm;
        float s = sS[o], t = sT[o];
        float2 p0 = unpack2(acc[mm][0]), p1 = unpack2(acc[mm][1]);
        size_t rowbase = (size_t)(b * 128 + o0 + o) * 4096 + n0;
        float4 rv = *(const float4*)(g_r + rowbase + tx * 4);
        float4 ov;
        float y;
        y = s * p0.x + t; y = (y > 0.f) ? y : 0.f; ov.x = y + rv.x;
        y = s * p0.y + t; y = (y > 0.f) ? y : 0.f; ov.y = y + rv.y;
        y = s * p1.x + t; y = (y > 0.f) ? y : 0.f; ov.z = y + rv.z;
        y = s * p1.y + t; y = (y > 0.f) ? y : 0.f; ov.w = y + rv.w;
        *(float4*)(out + rowbase + tx * 4) = ov;
    }
}

// ============================================================================
extern "C" void kernel_launch(void* const* d_in, const int* in_sizes, int n_in,
                              void* d_out, int out_size)
{
    const float* x = (const float*)d_in[0];
    k_prep<<<dim3(64, 2), 256>>>(x,
        (const float*)d_in[1], (const float*)d_in[2], (const float*)d_in[3],
        (const float*)d_in[4], (const float*)d_in[5],
        (const float*)d_in[6], (const float*)d_in[7], (const float*)d_in[8],
        (const float*)d_in[9], (const float*)d_in[10]);
    k_d2<<<dim3(64, 64, 4), 256>>>(x);
    k_topk<<<2048, 256>>>();
    k_gcn<<<2048, 256>>>(
        (const float*)d_in[11], (const float*)d_in[12], (const float*)d_in[13],
        (const float*)d_in[14], (const float*)d_in[15],
        (const float*)d_in[16], (const float*)d_in[17], (const float*)d_in[18],
        (const float*)d_in[19], (const float*)d_in[20]);
    k_dec<<<dim3(64, 2, 4), 256>>>(
        (const float*)d_in[21], (const float*)d_in[22], (const float*)d_in[23],
        (const float*)d_in[24], (const float*)d_in[25], (float*)d_out);
}

// round 13
// speedup vs baseline: 1.5267x; 1.0453x over previous
#include <cuda_runtime.h>
#include <cstdint>

#define FULLMASK 0xffffffffu

// ----- scratch: __device__ globals (no runtime allocation) ------------------
__device__ float  g_sq[4*4096];
__device__ float4 g_hb4[4*4096*4];              // bottleneck feats [p][16f]
__device__ float  g_r[4*128*4096];              // residual branch
__device__ float4 g_d2[(size_t)4*4096*1024];    // 256MB distance matrix
__device__ int    g_knn[4*4096*20];
__device__ float  g_allf[4*96*4096];

__device__ __forceinline__ void ffma2(unsigned long long &d, unsigned long long a, unsigned long long b) {
    asm("fma.rn.f32x2 %0, %1, %2, %0;" : "+l"(d) : "l"(a), "l"(b));
}
__device__ __forceinline__ unsigned long long pack2(float lo, float hi) {
    unsigned long long r; asm("mov.b64 %0, {%1, %2};" : "=l"(r) : "f"(lo), "f"(hi)); return r;
}
__device__ __forceinline__ float2 unpack2(unsigned long long v) {
    float2 f; asm("mov.b64 {%0, %1}, %2;" : "=f"(f.x), "=f"(f.y) : "l"(v)); return f;
}

// ============================================================================
// K1: sq, hb = relu(bn(Wbot@x)), r = relu(bn(Wres@x)). grid(64,2), 256 thr.
// ============================================================================
__global__ __launch_bounds__(256) void k_prep(
    const float* __restrict__ x,
    const float* __restrict__ Wres, const float* __restrict__ gres, const float* __restrict__ bres,
    const float* __restrict__ mres, const float* __restrict__ vres,
    const float* __restrict__ Wbot, const float* __restrict__ gbot, const float* __restrict__ bbot,
    const float* __restrict__ mbot, const float* __restrict__ vbot)
{
    __shared__ float4 sWr[64][16];
    __shared__ float4 sWb[16][16];
    __shared__ float sS[64], sT[64], sSb[16], sTb[16];
    const int tid = threadIdx.x;
    const int obase = blockIdx.y * 64;
    for (int i = tid; i < 1024; i += 256)
        sWr[i >> 4][i & 15] = ((const float4*)Wres)[(obase + (i >> 4)) * 16 + (i & 15)];
    sWb[tid >> 4][tid & 15] = ((const float4*)Wbot)[tid];
    if (tid < 64) {
        int o = obase + tid;
        float s = gres[o] * rsqrtf(vres[o] + 1e-5f);
        sS[tid] = s; sT[tid] = bres[o] - mres[o] * s;
    } else if (tid < 80) {
        int j = tid - 64;
        float s = gbot[j] * rsqrtf(vbot[j] + 1e-5f);
        sSb[j] = s; sTb[j] = bbot[j] - mbot[j] * s;
    }
    __syncthreads();

    const int p = blockIdx.x * 256 + tid;
    const int b = p >> 12, n = p & 4095;
    const float* xb = x + (size_t)b * 262144 + n;
    float xr[64]; float sqv = 0.f;
#pragma unroll
    for (int c = 0; c < 64; c++) { float v = xb[(size_t)c << 12]; xr[c] = v; sqv += v * v; }

    if (blockIdx.y == 0) {
        g_sq[p] = sqv;
        float h[16];
#pragma unroll
        for (int j = 0; j < 16; j++) {
            float acc = 0.f;
#pragma unroll
            for (int c4 = 0; c4 < 16; c4++) {
                float4 w = sWb[j][c4];
                acc += w.x * xr[4*c4] + w.y * xr[4*c4+1] + w.z * xr[4*c4+2] + w.w * xr[4*c4+3];
            }
            float y = sSb[j] * acc + sTb[j];
            h[j] = y > 0.f ? y : 0.f;
        }
        float4* hd = &g_hb4[(size_t)p * 4];
        hd[0] = make_float4(h[0], h[1], h[2], h[3]);
        hd[1] = make_float4(h[4], h[5], h[6], h[7]);
        hd[2] = make_float4(h[8], h[9], h[10], h[11]);
        hd[3] = make_float4(h[12], h[13], h[14], h[15]);
    }

    float* rp = g_r + (size_t)(b * 128 + obase) * 4096 + n;
    for (int o = 0; o < 64; o++) {
        float acc = 0.f;
#pragma unroll
        for (int c4 = 0; c4 < 16; c4++) {
            float4 w = sWr[o][c4];
            acc += w.x * xr[4*c4] + w.y * xr[4*c4+1] + w.z * xr[4*c4+2] + w.w * xr[4*c4+3];
        }
        float y = sS[o] * acc + sT[o];
        rp[(size_t)o << 12] = y > 0.f ? y : 0.f;
    }
}

// ============================================================================
// K2: d2 = sq_i + sq_j - 2<x_i,x_j>. SYMMETRY: only ti<=tj tiles computed;
// transposed tile written via smem transpose (bitwise-identical values).
// Inner loop: A pre-duplicated in smem -> zero ALU packs, pure FFMA2.
// S layout: [0..8191] As2 (dup pairs), [8192..12287] Bs. Ts aliases S after sync.
// ============================================================================
__global__ __launch_bounds__(256, 2) void k_d2(const float* __restrict__ x)
{
    __shared__ __align__(16) float S[12288];   // 48KB
    const int b = blockIdx.z;
    const int ti = blockIdx.y, tj = blockIdx.x;
    if (ti > tj) return;
    const int i0 = ti * 64, j0 = tj * 64;
    const int tid = threadIdx.x;
    const float4* xb = (const float4*)(x + (size_t)b * 262144);

#pragma unroll
    for (int t = 0; t < 4; t++) {
        int s = tid + t * 256;
        int c = s >> 4, r4 = s & 15;
        float4 va = xb[c * 1024 + (i0 >> 2) + r4];
        float4* da = (float4*)(S + c * 128 + r4 * 8);
        da[0] = make_float4(va.x, va.x, va.y, va.y);
        da[1] = make_float4(va.z, va.z, va.w, va.w);
        ((float4*)(S + 8192))[c * 16 + r4] = xb[c * 1024 + (j0 >> 2) + r4];
    }
    __syncthreads();

    const int tx = tid & 15, ty = tid >> 4;
    unsigned long long acc[4][2] = {{0ull,0ull},{0ull,0ull},{0ull,0ull},{0ull,0ull}};
#pragma unroll 8
    for (int k = 0; k < 64; k++) {
        ulonglong2 qa0 = *(const ulonglong2*)(S + k * 128 + ty * 8);       // dup(a0),dup(a1)
        ulonglong2 qa1 = *(const ulonglong2*)(S + k * 128 + ty * 8 + 4);   // dup(a2),dup(a3)
        ulonglong2 qb  = *(const ulonglong2*)(S + 8192 + k * 64 + tx * 4); // (b0,b1),(b2,b3)
        ffma2(acc[0][0], qa0.x, qb.x); ffma2(acc[0][1], qa0.x, qb.y);
        ffma2(acc[1][0], qa0.y, qb.x); ffma2(acc[1][1], qa0.y, qb.y);
        ffma2(acc[2][0], qa1.x, qb.x); ffma2(acc[2][1], qa1.x, qb.y);
        ffma2(acc[3][0], qa1.y, qb.x); ffma2(acc[3][1], qa1.y, qb.y);
    }

    __syncthreads();   // done with As2/Bs; S reusable as Ts[64][65]
    float* Ts = S;

    float4 sqj = ((const float4*)(g_sq + b * 4096 + j0))[tx];
    const int rbase = b * 4096 + i0 + ty * 4;
    const bool offdiag = (ti != tj);
#pragma unroll
    for (int mm = 0; mm < 4; mm++) {
        float2 p0 = unpack2(acc[mm][0]), p1 = unpack2(acc[mm][1]);
        float sqi = g_sq[rbase + mm];
        float4 o;
        o.x = sqi + sqj.x - 2.f * p0.x;
        o.y = sqi + sqj.y - 2.f * p0.y;
        o.z = sqi + sqj.z - 2.f * p1.x;
        o.w = sqi + sqj.w - 2.f * p1.y;
        g_d2[(size_t)(rbase + mm) * 1024 + (j0 >> 2) + tx] = o;
        if (offdiag) {
            float* tr = Ts + (ty * 4 + mm) * 65 + tx * 4;
            tr[0] = o.x; tr[1] = o.y; tr[2] = o.z; tr[3] = o.w;
        }
    }

    if (offdiag) {
        __syncthreads();
        float* gd = (float*)g_d2;
        const int rt = tid >> 2;            // j_local 0..63
        const int u0 = (tid & 3) * 4;       // i_local group base
        size_t rowbase = (size_t)(b * 4096 + j0 + rt) * 4096 + i0;
#pragma unroll
        for (int v = 0; v < 4; v++) {
            int c = u0 + v * 16;
            float4 w;
            w.x = Ts[(c + 0) * 65 + rt];
            w.y = Ts[(c + 1) * 65 + rt];
            w.z = Ts[(c + 2) * 65 + rt];
            w.w = Ts[(c + 3) * 65 + rt];
            *(float4*)(gd + rowbase + c) = w;
        }
    }
}

// ============================================================================
// K3: top-20 ascending (d2, idx) per row — lax.top_k semantics.
// Gate: one conservative ballot per float4; exact path only when it fires.
// ============================================================================
__global__ __launch_bounds__(256) void k_topk()
{
    const int gw = (blockIdx.x * 256 + threadIdx.x) >> 5;
    const int lane = threadIdx.x & 31;
    const float4* row = g_d2 + (size_t)gw * 1024;
    const float INF = __int_as_float(0x7f800000);
    float bd = INF; int bi = 0x7fffffff;
    float thr = INF; int thri = 0x7fffffff;
    for (int base = 0; base < 1024; base += 32) {
        float4 v4 = row[base + lane];
        int id0 = (base + lane) << 2;
        float mn = fminf(fminf(v4.x, v4.y), fminf(v4.z, v4.w));
        if (__ballot_sync(FULLMASK, mn <= thr)) {
            float vv[4] = {v4.x, v4.y, v4.z, v4.w};
#pragma unroll
            for (int j = 0; j < 4; j++) {
                float v = vv[j]; int id = id0 + j;
                unsigned m = __ballot_sync(FULLMASK, v < thr || (v == thr && id < thri));
                while (m) {
                    int src = __ffs(m) - 1;
                    float dn = __shfl_sync(FULLMASK, v, src);
                    int  idn = __shfl_sync(FULLMASK, id, src);
                    unsigned lt = __ballot_sync(FULLMASK, bd < dn || (bd == dn && bi < idn)) & 0xFFFFFu;
                    int pos = __popc(lt);
                    float pu = __shfl_up_sync(FULLMASK, bd, 1);
                    int   iu = __shfl_up_sync(FULLMASK, bi, 1);
                    if (lane < 20) {
                        if (lane == pos)      { bd = dn; bi = idn; }
                        else if (lane > pos)  { bd = pu; bi = iu; }
                    }
                    thr  = __shfl_sync(FULLMASK, bd, 19);
                    thri = __shfl_sync(FULLMASK, bi, 19);
                    m &= m - 1;
                    m &= __ballot_sync(FULLMASK, v < thr || (v == thr && id < thri));
                }
            }
        }
    }
    if (lane < 20) g_knn[(size_t)gw * 20 + lane] = bi;
}

// ============================================================================
// K4: warp/point edge convs; weights staged in padded smem.
// allf channels: [0..31]=o1, [32..63]=o2, [64..79]=max_k nb, [80..95]=ctr.
// ============================================================================
__global__ __launch_bounds__(256, 4) void k_gcn(
    const float* __restrict__ Wg1, const float* __restrict__ g1c, const float* __restrict__ b1c,
    const float* __restrict__ m1c, const float* __restrict__ v1c,
    const float* __restrict__ Wg2, const float* __restrict__ g2c, const float* __restrict__ b2c,
    const float* __restrict__ m2c, const float* __restrict__ v2c)
{
    __shared__ float sW1[32][33], sW2[32][33];
    __shared__ float sBN[4][32];
    __shared__ float4 Fb[8][21][4];
    const int tid = threadIdx.x, w = tid >> 5, lane = tid & 31;
    const int p = blockIdx.x * 8 + w, b = p >> 12, n = p & 4095;

    for (int i = tid; i < 1024; i += 256) {
        sW1[i >> 5][i & 31] = Wg1[i];
        sW2[i >> 5][i & 31] = Wg2[i];
    }
    if (tid < 32) {
        float s1v = g1c[tid] * rsqrtf(v1c[tid] + 1e-5f);
        float s2v = g2c[tid] * rsqrtf(v2c[tid] + 1e-5f);
        sBN[0][tid] = s1v; sBN[1][tid] = b1c[tid] - m1c[tid] * s1v;
        sBN[2][tid] = s2v; sBN[3][tid] = b2c[tid] - m2c[tid] * s2v;
    }
    __syncthreads();

    unsigned long long w1p[8], w2p[8];
#pragma unroll
    for (int c = 0; c < 8; c++) {
        w1p[c] = pack2(sW1[lane][2*c], sW1[lane][2*c + 1]);
        w2p[c] = pack2(sW2[lane][2*c], sW2[lane][2*c + 1]);
    }
    const float s1 = sBN[0][lane], t1 = sBN[1][lane];
    const float s2 = sBN[2][lane], t2 = sBN[3][lane];

    int id = (lane < 20) ? g_knn[(size_t)p * 20 + lane] : n;
#pragma unroll
    for (int it = 0; it < 3; it++) {
        int pc = it * 32 + lane;
        int k = pc >> 2;
        int srcn = __shfl_sync(FULLMASK, id, (k < 24) ? k : 0);
        if (pc < 84) Fb[w][k][pc & 3] = g_hb4[(size_t)(b * 4096 + srcn) * 4 + (pc & 3)];
    }
    __syncwarp();

    float cd1 = 0.f, cd2 = 0.f;
    {
        const float* cp = (const float*)Fb[w][20];
#pragma unroll
        for (int c = 0; c < 16; c++) {
            float cv = cp[c];
            cd1 += sW1[lane][16 + c] * cv;
            cd2 += sW2[lane][16 + c] * cv;
        }
    }

    const float NINF = __int_as_float(0xff800000);
    float o1 = NINF, o2 = NINF;
#pragma unroll
    for (int k = 0; k < 20; k++) {
        const float4* fq = Fb[w][k];
        float4 f0 = fq[0], f1 = fq[1], f2 = fq[2], f3 = fq[3];
        unsigned long long fp[8];
        fp[0] = pack2(f0.x, f0.y); fp[1] = pack2(f0.z, f0.w);
        fp[2] = pack2(f1.x, f1.y); fp[3] = pack2(f1.z, f1.w);
        fp[4] = pack2(f2.x, f2.y); fp[5] = pack2(f2.z, f2.w);
        fp[6] = pack2(f3.x, f3.y); fp[7] = pack2(f3.z, f3.w);

        unsigned long long a0 = 0ull, a1 = 0ull;
#pragma unroll
        for (int c = 0; c < 8; c += 2) { ffma2(a0, w1p[c], fp[c]); ffma2(a1, w1p[c+1], fp[c+1]); }
        float2 r0 = unpack2(a0), r1 = unpack2(a1);
        float y1 = s1 * (cd1 + (r0.x + r0.y) + (r1.x + r1.y)) + t1;
        y1 = (y1 > 0.f) ? y1 : 0.2f * y1;
        o1 = fmaxf(o1, y1);

        if ((k & 1) == 0) {
            unsigned long long c0 = 0ull, c1 = 0ull;
#pragma unroll
            for (int c = 0; c < 8; c += 2) { ffma2(c0, w2p[c], fp[c]); ffma2(c1, w2p[c+1], fp[c+1]); }
            float2 q0 = unpack2(c0), q1 = unpack2(c1);
            float y2 = s2 * (cd2 + (q0.x + q0.y) + (q1.x + q1.y)) + t2;
            y2 = (y2 > 0.f) ? y2 : 0.2f * y2;
            o2 = fmaxf(o2, y2);
        }
    }

    float gm;
    if (lane < 16) {
        gm = NINF;
#pragma unroll
        for (int k = 0; k < 20; k++) gm = fmaxf(gm, ((const float*)Fb[w][k])[lane]);
    } else {
        gm = ((const float*)Fb[w][20])[lane - 16];
    }

    float* ap = g_allf + (size_t)b * 96 * 4096 + n;
    ap[(size_t)lane * 4096]        = o1;
    ap[(size_t)(32 + lane) * 4096] = o2;
    ap[(size_t)(64 + lane) * 4096] = gm;
}

// ============================================================================
// K5: out = relu(bn(Wdec@allf)) + r — tiled GEMM 64x64x96, 4x4/thr, f32x2.
// ============================================================================
__global__ __launch_bounds__(256) void k_dec(
    const float* __restrict__ Wdec, const float* __restrict__ gd, const float* __restrict__ bdc,
    const float* __restrict__ md, const float* __restrict__ vd, float* __restrict__ out)
{
    __shared__ __align__(16) float sA[96 * 64];   // [c][o]
    __shared__ __align__(16) float sB[96 * 64];   // [c][n]
    __shared__ float sS[64], sT[64];
    const int b = blockIdx.z, o0 = blockIdx.y * 64, n0 = blockIdx.x * 64;
    const int tid = threadIdx.x;

    for (int i = tid; i < 6144; i += 256) {
        int c = i >> 6, o = i & 63;
        sA[c * 64 + o] = Wdec[(o0 + o) * 96 + c];
    }
    const float4* ab = (const float4*)(g_allf + (size_t)b * 96 * 4096);
    for (int i = tid; i < 1536; i += 256) {
        int c = i >> 4, r4 = i & 15;
        ((float4*)sB)[c * 16 + r4] = ab[c * 1024 + (n0 >> 2) + r4];
    }
    if (tid < 64) {
        int o = o0 + tid;
        float s = gd[o] * rsqrtf(vd[o] + 1e-5f);
        sS[tid] = s; sT[tid] = bdc[o] - md[o] * s;
    }
    __syncthreads();

    const int tx = tid & 15, ty = tid >> 4;
    unsigned long long acc[4][2] = {{0ull,0ull},{0ull,0ull},{0ull,0ull},{0ull,0ull}};
#pragma unroll 8
    for (int k = 0; k < 96; k++) {
        float4 av = *(const float4*)(sA + k * 64 + ty * 4);
        float4 bv = *(const float4*)(sB + k * 64 + tx * 4);
        unsigned long long b01 = pack2(bv.x, bv.y), b23 = pack2(bv.z, bv.w);
        unsigned long long aa;
        aa = pack2(av.x, av.x); ffma2(acc[0][0], aa, b01); ffma2(acc[0][1], aa, b23);
        aa = pack2(av.y, av.y); ffma2(acc[1][0], aa, b01); ffma2(acc[1][1], aa, b23);
        aa = pack2(av.z, av.z); ffma2(acc[2][0], aa, b01); ffma2(acc[2][1], aa, b23);
        aa = pack2(av.w, av.w); ffma2(acc[3][0], aa, b01); ffma2(acc[3][1], aa, b23);
    }

#pragma unroll
    for (int mm = 0; mm < 4; mm++) {
        int o = ty * 4 + mm;
        float s = sS[o], t = sT[o];
        float2 p0 = unpack2(acc[mm][0]), p1 = unpack2(acc[mm][1]);
        size_t rowbase = (size_t)(b * 128 + o0 + o) * 4096 + n0;
        float4 rv = *(const float4*)(g_r + rowbase + tx * 4);
        float4 ov;
        float y;
        y = s * p0.x + t; y = (y > 0.f) ? y : 0.f; ov.x = y + rv.x;
        y = s * p0.y + t; y = (y > 0.f) ? y : 0.f; ov.y = y + rv.y;
        y = s * p1.x + t; y = (y > 0.f) ? y : 0.f; ov.z = y + rv.z;
        y = s * p1.y + t; y = (y > 0.f) ? y : 0.f; ov.w = y + rv.w;
        *(float4*)(out + rowbase + tx * 4) = ov;
    }
}

// ============================================================================
extern "C" void kernel_launch(void* const* d_in, const int* in_sizes, int n_in,
                              void* d_out, int out_size)
{
    const float* x = (const float*)d_in[0];
    k_prep<<<dim3(64, 2), 256>>>(x,
        (const float*)d_in[1], (const float*)d_in[2], (const float*)d_in[3],
        (const float*)d_in[4], (const float*)d_in[5],
        (const float*)d_in[6], (const float*)d_in[7], (const float*)d_in[8],
        (const float*)d_in[9], (const float*)d_in[10]);
    k_d2<<<dim3(64, 64, 4), 256>>>(x);
    k_topk<<<2048, 256>>>();
    k_gcn<<<2048, 256>>>(
        (const float*)d_in[11], (const float*)d_in[12], (const float*)d_in[13],
        (const float*)d_in[14], (const float*)d_in[15],
        (const float*)d_in[16], (const float*)d_in[17], (const float*)d_in[18],
        (const float*)d_in[19], (const float*)d_in[20]);
    k_dec<<<dim3(64, 2, 4), 256>>>(
        (const float*)d_in[21], (const float*)d_in[22], (const float*)d_in[23],
        (const float*)d_in[24], (const float*)d_in[25], (float*)d_out);
}